// round 16
// baseline (speedup 1.0000x reference)
#include <cuda_runtime.h>
#include <cstdint>

#define THRESH 0.8f
#define DECAY  0.2f

constexpr int BSZ = 256;   // batch
constexpr int CH  = 4096;  // out features
constexpr int KD  = 4096;  // in features

// Scratch: two raw half-sums per plane. g_p[z][j][b][c], z = k-half.
// Fold (p0+p1)+bias happens in lif_kernel -- identical rounding order to the
// verified reference split-K=2 fold.
__device__ float g_p[2][3 * BSZ * CH];

typedef unsigned long long u64;

__device__ __forceinline__ u64 fma2(u64 a, u64 b, u64 c) {
    u64 d; asm("fma.rn.f32x2 %0, %1, %2, %3;" : "=l"(d) : "l"(a), "l"(b), "l"(c));
    return d;
}

// ---------------- GEMM half-chains: p[z][j][m][n] = sum_{k in half z} ...
// Each output's k-half is an ascending fused-FMA chain from zero (verified
// reference order). f32x2 packs two ADJACENT-N outputs per instruction:
// A is stored duplicated in smem ({a,a} pairs load directly, ty-broadcast);
// B n-pairs load directly as u64 (16B stride, conflict-free). Zero movs.
// BM=64 keeps W traffic minimal; BN=64 gives 1536 tiles -> 1.06x quantization.
constexpr int BM = 64, BN = 64, BK = 16;   // 128 threads, TM=8 x TN=4

__global__ __launch_bounds__(128, 8) void gemm3_kernel(
    const float* __restrict__ x,
    const float* __restrict__ W1,
    const float* __restrict__ W2,
    const float* __restrict__ W3)
{
    __shared__ float As2[BK][2 * BM];  // duplicated A   8 KB
    __shared__ float Bs[BK][BN];       // normal B       4 KB

    const int tid = threadIdx.x;
    const int bx  = blockIdx.x;    // 0..191  (j*64 + n-tile)
    const int by  = blockIdx.y;    // 0..3    (m-tile)
    const int bz  = blockIdx.z;    // 0..1    (k-half)

    const int j  = bx >> 6;
    const int n0 = (bx & 63) * BN;
    const int m0 = by * BM;

    const float* W = (j == 0) ? W1 : (j == 1) ? W2 : W3;

    const int tx = tid & 15;       // 16 -> n quad
    const int ty = tid >> 4;       // 8  -> m octet

    // fill coordinates: li = tid + l*128 (l = 0,1) covers 256 float4
    const int fRow = tid >> 2;                  // 0..31 (l adds +32)
    const int fK   = (tid & 3) * 4;             // 0,4,8,12
    const float* aPtr0 = x + (size_t)(m0 + fRow) * KD + fK;
    const float* aPtr1 = x + (size_t)(m0 + fRow + 32) * KD + fK;
    const float* bPtr0 = W + (size_t)(n0 + fRow) * KD + fK;
    const float* bPtr1 = W + (size_t)(n0 + fRow + 32) * KD + fK;

    // accumulators: 8 m rows x 2 n-pairs (lanes = n even/odd)
    u64 acc[8][2];
    #pragma unroll
    for (int p = 0; p < 8; p++) { acc[p][0] = 0ULL; acc[p][1] = 0ULL; }

    const int kbBeg = bz * 128;    // half = 2048 k = 128 BK-blocks
    const int kbEnd = kbBeg + 128;

    for (int kb = kbBeg; kb < kbEnd; kb++) {
        const int k0 = kb * BK;
        __syncthreads();   // prior compute done before overwrite

        // ---- fill A (duplicated) ----
        {
            float4 v0 = *(const float4*)(aPtr0 + k0);
            float4 v1 = *(const float4*)(aPtr1 + k0);
            ((float2*)&As2[fK + 0][2 * fRow])[0] = make_float2(v0.x, v0.x);
            ((float2*)&As2[fK + 1][2 * fRow])[0] = make_float2(v0.y, v0.y);
            ((float2*)&As2[fK + 2][2 * fRow])[0] = make_float2(v0.z, v0.z);
            ((float2*)&As2[fK + 3][2 * fRow])[0] = make_float2(v0.w, v0.w);
            ((float2*)&As2[fK + 0][2 * (fRow + 32)])[0] = make_float2(v1.x, v1.x);
            ((float2*)&As2[fK + 1][2 * (fRow + 32)])[0] = make_float2(v1.y, v1.y);
            ((float2*)&As2[fK + 2][2 * (fRow + 32)])[0] = make_float2(v1.z, v1.z);
            ((float2*)&As2[fK + 3][2 * (fRow + 32)])[0] = make_float2(v1.w, v1.w);
        }
        // ---- fill B (normal) ----
        {
            float4 v0 = *(const float4*)(bPtr0 + k0);
            float4 v1 = *(const float4*)(bPtr1 + k0);
            Bs[fK + 0][fRow] = v0.x; Bs[fK + 1][fRow] = v0.y;
            Bs[fK + 2][fRow] = v0.z; Bs[fK + 3][fRow] = v0.w;
            Bs[fK + 0][fRow + 32] = v1.x; Bs[fK + 1][fRow + 32] = v1.y;
            Bs[fK + 2][fRow + 32] = v1.z; Bs[fK + 3][fRow + 32] = v1.w;
        }
        __syncthreads();

        // ---- compute ----
        #pragma unroll
        for (int kk = 0; kk < BK; kk++) {
            ulonglong2 a01 = *(const ulonglong2*)(&As2[kk][16 * ty]);
            ulonglong2 a23 = *(const ulonglong2*)(&As2[kk][16 * ty + 4]);
            ulonglong2 a45 = *(const ulonglong2*)(&As2[kk][16 * ty + 8]);
            ulonglong2 a67 = *(const ulonglong2*)(&As2[kk][16 * ty + 12]);
            ulonglong2 b   = *(const ulonglong2*)(&Bs[kk][tx * 4]);
            u64 aa[8] = { a01.x, a01.y, a23.x, a23.y,
                          a45.x, a45.y, a67.x, a67.y };
            #pragma unroll
            for (int p = 0; p < 8; p++) {
                acc[p][0] = fma2(aa[p], b.x, acc[p][0]);
                acc[p][1] = fma2(aa[p], b.y, acc[p][1]);
            }
        }
    }

    // store raw half-sums (u64 pairs = bit-identical adjacent-n floats)
    float* yp = g_p[bz] + (size_t)j * BSZ * CH;
    #pragma unroll
    for (int p = 0; p < 8; p++) {
        int m = m0 + ty * 8 + p;
        ulonglong2 v = { acc[p][0], acc[p][1] };
        *(ulonglong2*)(yp + (size_t)m * CH + n0 + tx * 4) = v;
    }
}

// ---------------- LIF recurrence + split-K fold: one thread per (b,c) -------
__global__ __launch_bounds__(256) void lif_kernel(
    const float* __restrict__ b1, const float* __restrict__ b2,
    const float* __restrict__ b3,
    const float* __restrict__ Wlif, const float* __restrict__ blif,
    const int* __restrict__ winsPtr, float* __restrict__ out)
{
    const int idx = blockIdx.x * 256 + threadIdx.x;   // = b*CH + c
    const int b = idx >> 12;          // /CH
    const int c = idx & (CH - 1);

    // fold: y = (p0 + p1) + bias, separately rounded (reference order)
    const float y0 = __fadd_rn(__fadd_rn(g_p[0][idx],
                                         g_p[1][idx]), b1[c]);
    const float y1 = __fadd_rn(__fadd_rn(g_p[0][BSZ * CH + idx],
                                         g_p[1][BSZ * CH + idx]), b2[c]);
    const float y2 = __fadd_rn(__fadd_rn(g_p[0][2 * BSZ * CH + idx],
                                         g_p[1][2 * BSZ * CH + idx]), b3[c]);

    const float w0 = Wlif[0], w1 = Wlif[1], w2 = Wlif[2];
    const float bl = blif[0];
    const int wins = *winsPtr;

    float m0 = 0.f, m1 = 0.f, m2 = 0.f, m3 = 0.f;
    float s0 = 0.f, s1 = 0.f, s2 = 0.f, s3 = 0.f;

    float* o = out + (size_t)b * wins * (CH * 4) + (size_t)c * 4;

    for (int t = 0; t < wins; t++) {
        float inner = __fadd_rn(
            __fmaf_rn(m2, w2, __fmaf_rn(m1, w1, __fmul_rn(m0, w0))), bl);
        m0 = __fadd_rn(__fmul_rn(__fmul_rn(m0, DECAY), 1.f - s0), y0);
        m1 = __fadd_rn(__fmul_rn(__fmul_rn(m1, DECAY), 1.f - s1), y1);
        m2 = __fadd_rn(__fmul_rn(__fmul_rn(m2, DECAY), 1.f - s2), y2);
        m3 = __fadd_rn(__fmul_rn(__fmul_rn(m3, DECAY), 1.f - s3), inner);
        s0 = (m0 > THRESH) ? 1.f : 0.f;
        s1 = (m1 > THRESH) ? 1.f : 0.f;
        s2 = (m2 > THRESH) ? 1.f : 0.f;
        s3 = (m3 > THRESH) ? 1.f : 0.f;
        *(float4*)(o + (size_t)t * CH * 4) = make_float4(s0, s1, s2, s3);
    }
}

// ---------------- launch ----------------------------------------------------
extern "C" void kernel_launch(void* const* d_in, const int* in_sizes, int n_in,
                              void* d_out, int out_size) {
    const float* x    = (const float*)d_in[0];
    const float* W1   = (const float*)d_in[1];
    const float* b1   = (const float*)d_in[2];
    const float* W2   = (const float*)d_in[3];
    const float* b2   = (const float*)d_in[4];
    const float* W3   = (const float*)d_in[5];
    const float* b3   = (const float*)d_in[6];
    const float* Wlif = (const float*)d_in[7];
    const float* blif = (const float*)d_in[8];
    const int*   wins = (const int*)d_in[9];

    dim3 ggrid(192, 4, 2);   // 1536 CTAs, 128 threads each
    gemm3_kernel<<<ggrid, 128>>>(x, W1, W2, W3);
    lif_kernel<<<(BSZ * CH) / 256, 256>>>(b1, b2, b3, Wlif, blif, wins,
                                          (float*)d_out);
}

// round 17
// speedup vs baseline: 1.3318x; 1.3318x over previous
#include <cuda_runtime.h>
#include <cstdint>

#define THRESH 0.8f
#define DECAY  0.2f

constexpr int BSZ = 256;   // batch
constexpr int CH  = 4096;  // out features
constexpr int KD  = 4096;  // in features

// Scratch: two raw half-sums per plane. g_p[z][j][b][c], z = k-half.
// Fold (p0+p1)+bias happens in lif_kernel -- identical rounding order to the
// verified reference split-K=2 fold.
__device__ float g_p[2][3 * BSZ * CH];

typedef unsigned long long u64;

__device__ __forceinline__ u64 fma2(u64 a, u64 b, u64 c) {
    u64 d; asm("fma.rn.f32x2 %0, %1, %2, %3;" : "=l"(d) : "l"(a), "l"(b), "l"(c));
    return d;
}

// ---------------- GEMM half-chains: p[z][j][m][n] = sum_{k in half z} ...
// Each output's k-half is an ascending fused-FMA chain from zero (verified
// reference order). f32x2 packs two ADJACENT-N outputs per instruction:
// A is duplicated in smem so {a,a} pairs load directly (ty-broadcast);
// B n-pairs load directly as u64 (16B-stride, conflict-free). ZERO movs.
// Rows padded +4 floats: 16B-aligned, write conflicts 4-way -> 2-way.
constexpr int BM = 64, BN = 128, BK = 16;   // 128 threads, TM=8 x TN=8
constexpr int APAD = 2 * BM + 4;            // 132
constexpr int BPAD = BN + 4;                // 132

__global__ __launch_bounds__(128, 4) void gemm3_kernel(
    const float* __restrict__ x,
    const float* __restrict__ W1,
    const float* __restrict__ W2,
    const float* __restrict__ W3)
{
    __shared__ float As2[2][BK][APAD];  // duplicated A  ~16.9 KB
    __shared__ float Bs[2][BK][BPAD];   // normal B      ~16.9 KB

    const int tid = threadIdx.x;
    const int bx  = blockIdx.x;    // 0..95  (j*32 + n-tile)
    const int by  = blockIdx.y;    // 0..3   (m-tile)
    const int bz  = blockIdx.z;    // 0..1   (k-half)

    const int j  = bx >> 5;
    const int n0 = (bx & 31) * BN;
    const int m0 = by * BM;

    const float* W = (j == 0) ? W1 : (j == 1) ? W2 : W3;

    const int tx = tid & 15;       // 16 -> n position
    const int ty = tid >> 4;       // 8  -> m octet

    // global load coords (coalesced: 4 consecutive threads = 64B of one row)
    const int aRow = tid >> 2;             // 0..31 (+32 for second half)
    const int aK   = (tid & 3) * 4;
    const float* aPtr0 = x + (size_t)(m0 + aRow) * KD + aK;
    const float* aPtr1 = x + (size_t)(m0 + aRow + 32) * KD + aK;
    const float* bPtr[4];
    #pragma unroll
    for (int l = 0; l < 4; l++) {
        int li  = tid + l * 128;
        bPtr[l] = W + (size_t)(n0 + (li >> 2)) * KD + (li & 3) * 4;
    }

    // accumulators: 8 m rows x 4 n-pairs (lanes = adjacent n)
    u64 acc[8][4];
    #pragma unroll
    for (int p = 0; p < 8; p++)
        #pragma unroll
        for (int q = 0; q < 4; q++) acc[p][q] = 0ULL;

    const int kbBeg = bz * 128;    // half = 2048 k = 128 BK-blocks
    const int kbEnd = kbBeg + 128;

    // ---- prologue: load block kbBeg into buf 0 ----
    {
        const int k0 = kbBeg * BK;
        float4 a0 = *(const float4*)(aPtr0 + k0);
        float4 a1 = *(const float4*)(aPtr1 + k0);
        ((float2*)&As2[0][aK + 0][2 * aRow])[0] = make_float2(a0.x, a0.x);
        ((float2*)&As2[0][aK + 1][2 * aRow])[0] = make_float2(a0.y, a0.y);
        ((float2*)&As2[0][aK + 2][2 * aRow])[0] = make_float2(a0.z, a0.z);
        ((float2*)&As2[0][aK + 3][2 * aRow])[0] = make_float2(a0.w, a0.w);
        ((float2*)&As2[0][aK + 0][2 * (aRow + 32)])[0] = make_float2(a1.x, a1.x);
        ((float2*)&As2[0][aK + 1][2 * (aRow + 32)])[0] = make_float2(a1.y, a1.y);
        ((float2*)&As2[0][aK + 2][2 * (aRow + 32)])[0] = make_float2(a1.z, a1.z);
        ((float2*)&As2[0][aK + 3][2 * (aRow + 32)])[0] = make_float2(a1.w, a1.w);
        #pragma unroll
        for (int l = 0; l < 4; l++) {
            int li  = tid + l * 128;
            int row = li >> 2;
            int kq  = (li & 3) * 4;
            float4 v = *(const float4*)(bPtr[l] + k0);
            Bs[0][kq + 0][row] = v.x; Bs[0][kq + 1][row] = v.y;
            Bs[0][kq + 2][row] = v.z; Bs[0][kq + 3][row] = v.w;
        }
    }
    __syncthreads();

    int buf = 0;
    for (int kb = kbBeg; kb < kbEnd; kb++) {
        const bool more = (kb + 1 < kbEnd);
        float4 a0, a1, bv[4];
        if (more) {
            const int k1 = (kb + 1) * BK;
            a0 = *(const float4*)(aPtr0 + k1);
            a1 = *(const float4*)(aPtr1 + k1);
            #pragma unroll
            for (int l = 0; l < 4; l++) bv[l] = *(const float4*)(bPtr[l] + k1);
        }

        // ---- compute current block (zero packing movs) ----
        #pragma unroll
        for (int kk = 0; kk < BK; kk++) {
            ulonglong2 a01 = *(const ulonglong2*)(&As2[buf][kk][16 * ty]);
            ulonglong2 a23 = *(const ulonglong2*)(&As2[buf][kk][16 * ty + 4]);
            ulonglong2 a45 = *(const ulonglong2*)(&As2[buf][kk][16 * ty + 8]);
            ulonglong2 a67 = *(const ulonglong2*)(&As2[buf][kk][16 * ty + 12]);
            ulonglong2 b0  = *(const ulonglong2*)(&Bs[buf][kk][tx * 4]);
            ulonglong2 b1  = *(const ulonglong2*)(&Bs[buf][kk][64 + tx * 4]);
            u64 aa[8] = { a01.x, a01.y, a23.x, a23.y,
                          a45.x, a45.y, a67.x, a67.y };
            u64 bb[4] = { b0.x, b0.y, b1.x, b1.y };
            #pragma unroll
            for (int p = 0; p < 8; p++)
                #pragma unroll
                for (int q = 0; q < 4; q++)
                    acc[p][q] = fma2(aa[p], bb[q], acc[p][q]);
        }

        // ---- stage next block into the free buffer ----
        if (more) {
            int nb = buf ^ 1;
            ((float2*)&As2[nb][aK + 0][2 * aRow])[0] = make_float2(a0.x, a0.x);
            ((float2*)&As2[nb][aK + 1][2 * aRow])[0] = make_float2(a0.y, a0.y);
            ((float2*)&As2[nb][aK + 2][2 * aRow])[0] = make_float2(a0.z, a0.z);
            ((float2*)&As2[nb][aK + 3][2 * aRow])[0] = make_float2(a0.w, a0.w);
            ((float2*)&As2[nb][aK + 0][2 * (aRow + 32)])[0] = make_float2(a1.x, a1.x);
            ((float2*)&As2[nb][aK + 1][2 * (aRow + 32)])[0] = make_float2(a1.y, a1.y);
            ((float2*)&As2[nb][aK + 2][2 * (aRow + 32)])[0] = make_float2(a1.z, a1.z);
            ((float2*)&As2[nb][aK + 3][2 * (aRow + 32)])[0] = make_float2(a1.w, a1.w);
            #pragma unroll
            for (int l = 0; l < 4; l++) {
                int li  = tid + l * 128;
                int row = li >> 2;
                int kq  = (li & 3) * 4;
                Bs[nb][kq + 0][row] = bv[l].x; Bs[nb][kq + 1][row] = bv[l].y;
                Bs[nb][kq + 2][row] = bv[l].z; Bs[nb][kq + 3][row] = bv[l].w;
            }
        }
        __syncthreads();
        buf ^= 1;
    }

    // store raw half-sums (u64 = bit-identical adjacent-n float pairs)
    float* yp = g_p[bz] + (size_t)j * BSZ * CH;
    #pragma unroll
    for (int p = 0; p < 8; p++) {
        int m = m0 + ty * 8 + p;
        float* r = yp + (size_t)m * CH + n0;
        ulonglong2 v0 = { acc[p][0], acc[p][1] };
        ulonglong2 v1 = { acc[p][2], acc[p][3] };
        *(ulonglong2*)(r + tx * 4)      = v0;
        *(ulonglong2*)(r + 64 + tx * 4) = v1;
    }
}

// ---------------- LIF recurrence + split-K fold: one thread per (b,c) -------
__global__ __launch_bounds__(256) void lif_kernel(
    const float* __restrict__ b1, const float* __restrict__ b2,
    const float* __restrict__ b3,
    const float* __restrict__ Wlif, const float* __restrict__ blif,
    const int* __restrict__ winsPtr, float* __restrict__ out)
{
    const int idx = blockIdx.x * 256 + threadIdx.x;   // = b*CH + c
    const int b = idx >> 12;          // /CH
    const int c = idx & (CH - 1);

    // fold: y = (p0 + p1) + bias, separately rounded (reference order)
    const float y0 = __fadd_rn(__fadd_rn(g_p[0][idx],
                                         g_p[1][idx]), b1[c]);
    const float y1 = __fadd_rn(__fadd_rn(g_p[0][BSZ * CH + idx],
                                         g_p[1][BSZ * CH + idx]), b2[c]);
    const float y2 = __fadd_rn(__fadd_rn(g_p[0][2 * BSZ * CH + idx],
                                         g_p[1][2 * BSZ * CH + idx]), b3[c]);

    const float w0 = Wlif[0], w1 = Wlif[1], w2 = Wlif[2];
    const float bl = blif[0];
    const int wins = *winsPtr;

    float m0 = 0.f, m1 = 0.f, m2 = 0.f, m3 = 0.f;
    float s0 = 0.f, s1 = 0.f, s2 = 0.f, s3 = 0.f;

    float* o = out + (size_t)b * wins * (CH * 4) + (size_t)c * 4;

    for (int t = 0; t < wins; t++) {
        float inner = __fadd_rn(
            __fmaf_rn(m2, w2, __fmaf_rn(m1, w1, __fmul_rn(m0, w0))), bl);
        m0 = __fadd_rn(__fmul_rn(__fmul_rn(m0, DECAY), 1.f - s0), y0);
        m1 = __fadd_rn(__fmul_rn(__fmul_rn(m1, DECAY), 1.f - s1), y1);
        m2 = __fadd_rn(__fmul_rn(__fmul_rn(m2, DECAY), 1.f - s2), y2);
        m3 = __fadd_rn(__fmul_rn(__fmul_rn(m3, DECAY), 1.f - s3), inner);
        s0 = (m0 > THRESH) ? 1.f : 0.f;
        s1 = (m1 > THRESH) ? 1.f : 0.f;
        s2 = (m2 > THRESH) ? 1.f : 0.f;
        s3 = (m3 > THRESH) ? 1.f : 0.f;
        *(float4*)(o + (size_t)t * CH * 4) = make_float4(s0, s1, s2, s3);
    }
}

// ---------------- launch ----------------------------------------------------
extern "C" void kernel_launch(void* const* d_in, const int* in_sizes, int n_in,
                              void* d_out, int out_size) {
    const float* x    = (const float*)d_in[0];
    const float* W1   = (const float*)d_in[1];
    const float* b1   = (const float*)d_in[2];
    const float* W2   = (const float*)d_in[3];
    const float* b2   = (const float*)d_in[4];
    const float* W3   = (const float*)d_in[5];
    const float* b3   = (const float*)d_in[6];
    const float* Wlif = (const float*)d_in[7];
    const float* blif = (const float*)d_in[8];
    const int*   wins = (const int*)d_in[9];

    dim3 ggrid(96, 4, 2);   // 768 CTAs, 128 threads each
    gemm3_kernel<<<ggrid, 128>>>(x, W1, W2, W3);
    lif_kernel<<<(BSZ * CH) / 256, 256>>>(b1, b2, b3, Wlif, blif, wins,
                                          (float*)d_out);
}